// round 7
// baseline (speedup 1.0000x reference)
#include <cuda_runtime.h>
#include <cuda_bf16.h>
#include <stdint.h>

#define N_NODES_C  100000
#define N_GRAPHS_C 128
#define D_NODE 96
#define D_EDGE 32
#define HID 16
#define BN_EPS 1e-5f

#define TILE 256
#define THREADS 128       // EPT=2
#define RSTRIDE 52        // floats per edge row: 32 attr + 16 p + 4 pad
#define NT 256
#define NSLOT 32          // bin slots per graph (128B stride)

// ---- folded parameters ----
struct CP {
    float W[D_EDGE][HID];    // folded edge-part of W1, [j][k] (k-pairs contiguous)
    float B[HID];
    float W2[HID];
    float b2;
    float pad[3];
    float Wx[HID][D_NODE];
};
__constant__ CP c_par;
__device__   CP g_par;

__device__ float g_p[N_NODES_C * HID];            // 6.4 MB
__device__ float g_bins[N_GRAPHS_C * NSLOT];      // zero-init; finish re-zeroes

typedef unsigned long long u64;

__device__ __forceinline__ u64 add2(u64 x, u64 y) {
    u64 r; asm("add.rn.f32x2 %0,%1,%2;" : "=l"(r) : "l"(x), "l"(y)); return r;
}

// -------- fold BN into weights --------
__global__ void prep_kernel(const float* __restrict__ W1, const float* __restrict__ b1,
                            const float* __restrict__ gamma, const float* __restrict__ beta,
                            const float* __restrict__ rm, const float* __restrict__ rv,
                            const float* __restrict__ W2, const float* __restrict__ b2) {
    __shared__ float a[HID];
    int lt = threadIdx.x;
    int t  = blockIdx.x * blockDim.x + lt;
    int stride = gridDim.x * blockDim.x;
    if (lt < HID) a[lt] = gamma[lt] * rsqrtf(rv[lt] + BN_EPS);
    __syncthreads();
    for (int i = t; i < D_EDGE * HID; i += stride) {
        int j = i / HID, k = i % HID;
        g_par.W[j][k] = a[k] * W1[k * (D_NODE + D_EDGE) + D_NODE + j];
    }
    for (int i = t; i < HID * D_NODE; i += stride) {
        int k = i / D_NODE, j = i % D_NODE;
        g_par.Wx[k][j] = a[k] * W1[k * (D_NODE + D_EDGE) + j];
    }
    if (t < HID) {
        g_par.B[t]  = a[t] * (b1[t] - rm[t]) + beta[t];
        g_par.W2[t] = W2[t];
    }
    if (t == 0) g_par.b2 = b2[0];
}

// -------- per-node: p[n][k] = Wx'[k] . x[n] --------
__global__ void __launch_bounds__(NT) node_kernel(const float* __restrict__ x, int n_nodes) {
    int n = blockIdx.x * blockDim.x + threadIdx.x;
    if (n >= n_nodes) return;
    float acc[HID];
#pragma unroll
    for (int k = 0; k < HID; k++) acc[k] = 0.0f;
    const float4* xr = (const float4*)(x + (size_t)n * D_NODE);
#pragma unroll
    for (int jj = 0; jj < D_NODE / 4; jj++) {
        float4 v = __ldg(xr + jj);
#pragma unroll
        for (int k = 0; k < HID; k++) {
            acc[k] += c_par.Wx[k][jj*4+0] * v.x + c_par.Wx[k][jj*4+1] * v.y
                    + c_par.Wx[k][jj*4+2] * v.z + c_par.Wx[k][jj*4+3] * v.w;
        }
    }
    float4* po = (float4*)(g_p + (size_t)n * HID);
    po[0] = make_float4(acc[0], acc[1], acc[2], acc[3]);
    po[1] = make_float4(acc[4], acc[5], acc[6], acc[7]);
    po[2] = make_float4(acc[8], acc[9], acc[10], acc[11]);
    po[3] = make_float4(acc[12], acc[13], acc[14], acc[15]);
}

// -------- per-edge: EPT=2, packed-pair MLP, weights amortized over 2 edges --------
__global__ void __launch_bounds__(THREADS) edge_kernel(
    const float* __restrict__ edge_attr,
    const int* __restrict__ ei,             // [2][E] int32
    const int* __restrict__ batch,          // [N]    int32
    int n_edges) {
    extern __shared__ float sm[];
    float* sRow = sm;                                   // TILE * RSTRIDE floats
    int*   sSrc = (int*)(sm + TILE * RSTRIDE);          // TILE

    const int t    = threadIdx.x;
    const int lane = t & 31;
    const int e0   = blockIdx.x * TILE;
    const int eA   = e0 + t;
    const int eB   = e0 + t + THREADS;
    const bool vA  = eA < n_edges;
    const bool vB  = eB < n_edges;

    int gA = 0, gB = 0;
    {
        int sA = 0, sB = 0;
        if (vA) { sA = __ldg(ei + eA); gA = __ldg(batch + __ldg(ei + n_edges + eA)); }
        if (vB) { sB = __ldg(ei + eB); gB = __ldg(batch + __ldg(ei + n_edges + eB)); }
        sSrc[t] = sA;
        sSrc[t + THREADS] = sB;
    }
    __syncthreads();

    // cooperative p gather first (random L2 latency overlaps attr DRAM stream)
    {
#pragma unroll
        for (int r = 0; r < (TILE * 4) / THREADS; r++) {              // 8 rounds
            int idx = r * THREADS + t;
            int el  = idx >> 2;
            int q   = idx & 3;
            int s   = sSrc[el];
            float4 pv = __ldg((const float4*)g_p + (size_t)s * 4 + q);
            *(float4*)(sRow + el * RSTRIDE + D_EDGE + q * 4) = pv;
        }
        const float4* ga = (const float4*)edge_attr;
        const long long base  = (long long)e0 * (D_EDGE / 4);
        const long long total = (long long)n_edges * (D_EDGE / 4);
#pragma unroll
        for (int r = 0; r < (TILE * (D_EDGE / 4)) / THREADS; r++) {   // 16 rounds
            int idx = r * THREADS + t;
            float4 w = make_float4(0.f, 0.f, 0.f, 0.f);
            if (base + idx < total) w = __ldg(ga + base + idx);
            int el = idx >> 3;
            int c  = idx & 7;
            *(float4*)(sRow + el * RSTRIDE + c * 4) = w;
        }
    }
    __syncthreads();

    const float* rowA = sRow + t * RSTRIDE;
    const float* rowB = sRow + (t + THREADS) * RSTRIDE;
    const u64* cw = (const u64*)&c_par.W[0][0];     // [j][pair]
    const u64* cb = (const u64*)&c_par.B[0];

    // acc pairs = p + bias  (both edges)
    u64 A[8], Bv[8];
#pragma unroll
    for (int q = 0; q < 2; q++) {
        ulonglong2 a0 = *(const ulonglong2*)(rowA + D_EDGE + q * 8);
        ulonglong2 a1 = *(const ulonglong2*)(rowA + D_EDGE + q * 8 + 4);
        ulonglong2 b0 = *(const ulonglong2*)(rowB + D_EDGE + q * 8);
        ulonglong2 b1 = *(const ulonglong2*)(rowB + D_EDGE + q * 8 + 4);
        A[q*4+0]  = add2(a0.x, cb[q*4+0]); A[q*4+1]  = add2(a0.y, cb[q*4+1]);
        A[q*4+2]  = add2(a1.x, cb[q*4+2]); A[q*4+3]  = add2(a1.y, cb[q*4+3]);
        Bv[q*4+0] = add2(b0.x, cb[q*4+0]); Bv[q*4+1] = add2(b0.y, cb[q*4+1]);
        Bv[q*4+2] = add2(b1.x, cb[q*4+2]); Bv[q*4+3] = add2(b1.y, cb[q*4+3]);
    }

    // j-loop: each weight pair fetched once, used for BOTH edges
#pragma unroll
    for (int c = 0; c < 8; c++) {
        float4 a4 = *(const float4*)(rowA + c * 4);
        float4 b4 = *(const float4*)(rowB + c * 4);
        float avA[4] = {a4.x, a4.y, a4.z, a4.w};
        float avB[4] = {b4.x, b4.y, b4.z, b4.w};
#pragma unroll
        for (int jj = 0; jj < 4; jj++) {
            u64 dupA, dupB;
            asm("mov.b64 %0,{%1,%1};" : "=l"(dupA) : "f"(avA[jj]));
            asm("mov.b64 %0,{%1,%1};" : "=l"(dupB) : "f"(avB[jj]));
            const u64* wrow = cw + (c*4 + jj) * 8;
#pragma unroll
            for (int p = 0; p < 8; p++) {
                u64 w = wrow[p];
                asm("fma.rn.f32x2 %0,%1,%2,%0;" : "+l"(A[p])  : "l"(w), "l"(dupA));
                asm("fma.rn.f32x2 %0,%1,%2,%0;" : "+l"(Bv[p]) : "l"(w), "l"(dupB));
            }
        }
    }

    if (vA) {
        float m = c_par.b2;
#pragma unroll
        for (int p = 0; p < 8; p++) {
            float lo, hi;
            asm("mov.b64 {%0,%1},%2;" : "=f"(lo), "=f"(hi) : "l"(A[p]));
            m = fmaf(c_par.W2[2*p],   fmaxf(lo, 0.0f), m);
            m = fmaf(c_par.W2[2*p+1], fmaxf(hi, 0.0f), m);
        }
        atomicAdd(&g_bins[gA * NSLOT + lane], m);
    }
    if (vB) {
        float m = c_par.b2;
#pragma unroll
        for (int p = 0; p < 8; p++) {
            float lo, hi;
            asm("mov.b64 {%0,%1},%2;" : "=f"(lo), "=f"(hi) : "l"(Bv[p]));
            m = fmaf(c_par.W2[2*p],   fmaxf(lo, 0.0f), m);
            m = fmaf(c_par.W2[2*p+1], fmaxf(hi, 0.0f), m);
        }
        atomicAdd(&g_bins[gB * NSLOT + lane], m);
    }
}

// -------- finish: one block per graph, warp reduce, write + re-zero --------
__global__ void finish_kernel(float* __restrict__ out) {
    int g = blockIdx.x;
    int lane = threadIdx.x;
    float s = g_bins[g * NSLOT + lane];
    g_bins[g * NSLOT + lane] = 0.0f;
#pragma unroll
    for (int m = 16; m >= 1; m >>= 1) s += __shfl_xor_sync(0xffffffffu, s, m);
    if (lane == 0) out[g] = s;
}

#define EDGE_SMEM (TILE * RSTRIDE * 4 + TILE * 4)

extern "C" void kernel_launch(void* const* d_in, const int* in_sizes, int n_in,
                              void* d_out, int out_size) {
    const float* x         = (const float*)d_in[0];
    const float* edge_attr = (const float*)d_in[1];
    const int*   ei        = (const int*)d_in[2];
    const int*   batch     = (const int*)d_in[3];
    const float* W1        = (const float*)d_in[4];
    const float* b1        = (const float*)d_in[5];
    const float* gamma     = (const float*)d_in[6];
    const float* beta      = (const float*)d_in[7];
    const float* rm        = (const float*)d_in[8];
    const float* rv        = (const float*)d_in[9];
    const float* W2        = (const float*)d_in[10];
    const float* b2        = (const float*)d_in[11];
    float* out = (float*)d_out;

    const int n_nodes = in_sizes[0] / D_NODE;
    const int n_edges = in_sizes[1] / D_EDGE;

    cudaFuncSetAttribute(edge_kernel, cudaFuncAttributeMaxDynamicSharedMemorySize, EDGE_SMEM);

    void *c_addr = nullptr, *g_addr = nullptr;
    cudaGetSymbolAddress(&c_addr, c_par);
    cudaGetSymbolAddress(&g_addr, g_par);

    prep_kernel<<<8, 256>>>(W1, b1, gamma, beta, rm, rv, W2, b2);
    cudaMemcpyAsync(c_addr, g_addr, sizeof(CP), cudaMemcpyDeviceToDevice, 0);
    node_kernel<<<(n_nodes + NT - 1) / NT, NT>>>(x, n_nodes);
    edge_kernel<<<(n_edges + TILE - 1) / TILE, THREADS, EDGE_SMEM>>>(edge_attr, ei, batch, n_edges);
    finish_kernel<<<N_GRAPHS_C, NSLOT>>>(out);
}